// round 10
// baseline (speedup 1.0000x reference)
#include <cuda_runtime.h>
#include <cstdint>

#define N_ROWS 1000000
#define NTHREADS 320
#define WARPS 10
#define ROWS_PER_WARP 32
#define TILE_ROWS 320
#define NTILES ((N_ROWS + TILE_ROWS - 1) / TILE_ROWS)   // 3125 exactly
#define GRID 152

// smem: W repacked [3][8ks][4q][32j] uint4 = 49152 B
//       A: per warp 2 buffers x (32 rows x 64 fp32) = 2 x 8192 B
//       bias 256 B
#define SMEM_W_BYTES  49152
#define SMEM_A_OFF    SMEM_W_BYTES
#define SMEM_A_BYTES  (WARPS * 2 * 8192)
#define SMEM_BIAS_OFF (SMEM_A_OFF + SMEM_A_BYTES)
#define SMEM_TOTAL    (SMEM_BIAS_OFF + 256)             // 213504 B -> 1 CTA/SM

__device__ __forceinline__ uint32_t tf32r(float f) {
    uint32_t u;
    asm("cvt.rna.tf32.f32 %0, %1;" : "=r"(u) : "f"(f));
    return u;
}

__device__ __forceinline__ uint32_t smem_u32(const void* p) {
    uint32_t a;
    asm("{ .reg .u64 t; cvta.to.shared.u64 t, %1; cvt.u32.u64 %0, t; }"
        : "=r"(a) : "l"(p));
    return a;
}

__device__ __forceinline__ void mma1688(float* d, const uint32_t* a, uint32_t b0, uint32_t b1) {
    asm volatile(
        "mma.sync.aligned.m16n8k8.row.col.f32.tf32.tf32.f32 "
        "{%0,%1,%2,%3}, {%4,%5,%6,%7}, {%8,%9}, {%0,%1,%2,%3};"
        : "+f"(d[0]), "+f"(d[1]), "+f"(d[2]), "+f"(d[3])
        : "r"(a[0]), "r"(a[1]), "r"(a[2]), "r"(a[3]), "r"(b0), "r"(b1));
}

__device__ __forceinline__ void cpasync16(uint32_t dst, const void* src) {
    asm volatile("cp.async.cg.shared.global [%0], [%1], 16;" :: "r"(dst), "l"(src));
}
__device__ __forceinline__ void cp_commit() {
    asm volatile("cp.async.commit_group;" ::: "memory");
}
__device__ __forceinline__ void cp_wait1() {
    asm volatile("cp.async.wait_group 1;" ::: "memory");
}

// Gather 32 rows; 16 lanes cover one row's 16 chunks -> 2 contiguous-dst rows per
// cp.async step (4 cache lines each). Row indices broadcast via shfl.
// dst chunk swizzle: c -> c ^ (row & 15).
__device__ __forceinline__ void issue_stage_idx(uint32_t bufb, const float* __restrict__ x,
                                                int idxreg, int l) {
    const int sub = l >> 4;
    const int c = l & 15;
#pragma unroll
    for (int i = 0; i < 16; i++) {
        const int rl = 2 * i + sub;  // row within 32-row tile
        const int src = __shfl_sync(0xffffffffu, idxreg, rl);
        const uint32_t dst = bufb + (uint32_t)rl * 256u + ((uint32_t)(c ^ (rl & 15)) << 4);
        cpasync16(dst, reinterpret_cast<const char*>(x + (size_t)src * 64) + c * 16);
    }
}

// Identity gather: rows base2 + rl (clamped).
__device__ __forceinline__ void issue_stage_id(uint32_t bufb, const float* __restrict__ x,
                                               int base2, int l) {
    const int sub = l >> 4;
    const int c = l & 15;
#pragma unroll
    for (int i = 0; i < 16; i++) {
        const int rl = 2 * i + sub;
        int src = base2 + rl;
        if (src >= N_ROWS) src = N_ROWS - 1;
        const uint32_t dst = bufb + (uint32_t)rl * 256u + ((uint32_t)(c ^ (rl & 15)) << 4);
        cpasync16(dst, reinterpret_cast<const char*>(x + (size_t)src * 64) + c * 16);
    }
}

// one t-stage: 32 rows x 64 cols x 64 k. A fp32 in smem (swizzled), cvt.rna here.
// B LDS swizzle ^(q<<1): conflict-free phases.
__device__ __forceinline__ void mma_stage(const float* __restrict__ sA,
                                          const uint4* __restrict__ sWt,
                                          float acc[2][8][4], int g, int q) {
#pragma unroll
    for (int ks = 0; ks < 8; ks++) {
        uint32_t a[2][4];
#pragma unroll
        for (int m = 0; m < 2; m++) {
            const int r0 = m * 16 + g;       // r0 & 15 == g
            const int r1 = r0 + 8;           // r1 & 15 == g + 8
            a[m][0] = tf32r(sA[r0 * 64 + (((2 * ks) ^ g) << 2) + q]);
            a[m][1] = tf32r(sA[r1 * 64 + (((2 * ks) ^ (g + 8)) << 2) + q]);
            a[m][2] = tf32r(sA[r0 * 64 + (((2 * ks + 1) ^ g) << 2) + q]);
            a[m][3] = tf32r(sA[r1 * 64 + (((2 * ks + 1) ^ (g + 8)) << 2) + q]);
        }
        const uint4* bp = sWt + (ks * 4 + q) * 32;
#pragma unroll
        for (int nbl = 0; nbl < 4; nbl++) {
            const uint4 bv = bp[(nbl * 8 + g) ^ (q << 1)];
            mma1688(acc[0][nbl], a[0], bv.x, bv.y);
            mma1688(acc[0][nbl + 4], a[0], bv.z, bv.w);
            mma1688(acc[1][nbl], a[1], bv.x, bv.y);
            mma1688(acc[1][nbl + 4], a[1], bv.z, bv.w);
        }
    }
}

__global__ void __launch_bounds__(NTHREADS, 1)
polyconv_kernel(const float* __restrict__ x,
                const int* __restrict__ li,
                const int* __restrict__ ri,
                const float* __restrict__ W,
                const float* __restrict__ bias,
                float* __restrict__ out) {
    extern __shared__ char smem[];
    uint4* sW4 = reinterpret_cast<uint4*>(smem);   // [3][8][4][32] uint4
    const int tid = threadIdx.x;
    const int w = tid >> 5;
    const int l = tid & 31;
    float* sA = reinterpret_cast<float*>(smem + SMEM_A_OFF + w * 16384);  // 2 bufs x 2048 fp32
    float* sbias = reinterpret_cast<float*>(smem + SMEM_BIAS_OFF);
    const uint32_t sAu = smem_u32(sA);

    // ---- stage W: sW4[t][ks][q][j] = (W[k][n], W[k+4][n], W[k][n+32], W[k+4][n+32]),
    //      n = j ^ (q<<1), k = ks*8+q ; W gmem: W[n][t*64 + k]
    for (int i = tid; i < 3 * 8 * 4 * 32; i += NTHREADS) {
        const int j = i & 31;
        const int q = (i >> 5) & 3;
        const int ks = (i >> 7) & 7;
        const int t = i >> 10;
        const int n = j ^ (q << 1);
        const int k = ks * 8 + q;
        const float* wp = W + t * 64 + k;
        uint4 v;
        v.x = tf32r(wp[n * 192]);
        v.y = tf32r(wp[n * 192 + 4]);
        v.z = tf32r(wp[(n + 32) * 192]);
        v.w = tf32r(wp[(n + 32) * 192 + 4]);
        sW4[i] = v;
    }
    if (tid < 64) sbias[tid] = bias[tid];
    __syncthreads();

    const int q = l & 3;
    const int g = l >> 2;

    float acc[2][8][4];
#pragma unroll
    for (int m = 0; m < 2; m++)
#pragma unroll
        for (int nb = 0; nb < 8; nb++)
#pragma unroll
            for (int jj = 0; jj < 4; jj++) acc[m][nb][jj] = 0.0f;

    // ---- prologue ----
    int tile = blockIdx.x;
    int base2 = tile * TILE_ROWS + w * ROWS_PER_WARP;
    int idxrow = base2 + l;
    if (idxrow >= N_ROWS) idxrow = N_ROWS - 1;
    int ilc = __ldg(li + idxrow);   // per-lane: index for row l of this warp tile
    int irc = __ldg(ri + idxrow);
    issue_stage_id(sAu, x, base2, l);
    cp_commit();
    uint32_t cur = 0;

    while (true) {
        const int ntile = tile + GRID;
        const bool nv = (ntile < NTILES);
        const int nbase2 = (nv ? ntile : tile) * TILE_ROWS + w * ROWS_PER_WARP;
        int nidxrow = nbase2 + l;
        if (nidxrow >= N_ROWS) nidxrow = N_ROWS - 1;
        const int iln = __ldg(li + nidxrow);
        const int irn = __ldg(ri + nidxrow);

        const float* bufc = sA + (cur ? 2048 : 0);
        const float* bufo = sA + (cur ? 0 : 2048);
        const uint32_t bufcu = sAu + (cur ? 8192u : 0u);
        const uint32_t bufou = sAu + (cur ? 0u : 8192u);

        // ---- t0 (x) ----
        issue_stage_idx(bufou, x, ilc, l);   // t1 -> other buf
        cp_commit();
        cp_wait1();
        __syncwarp();
        mma_stage(bufc, sW4, acc, g, q);
        __syncwarp();
        // ---- t1 (x[L]) ----
        issue_stage_idx(bufcu, x, irc, l);   // t2 -> cur buf
        cp_commit();
        cp_wait1();
        __syncwarp();
        mma_stage(bufo, sW4 + 1024, acc, g, q);
        __syncwarp();
        // ---- t2 (x[R]) ----
        issue_stage_id(bufou, x, nbase2, l); // next t0 -> other buf
        cp_commit();
        cp_wait1();
        __syncwarp();
        mma_stage(bufc, sW4 + 2048, acc, g, q);

        // ---- epilogue: bias + streaming store (evict-first: keep L2 for x) ----
        const int rowb = base2 + g;
#pragma unroll
        for (int nb = 0; nb < 8; nb++) {
            const int col = nb * 8 + q * 2;
            const float2 bb = *reinterpret_cast<const float2*>(sbias + col);
#pragma unroll
            for (int m = 0; m < 2; m++) {
                const int r0 = rowb + m * 16;
                if (r0 < N_ROWS) {
                    float2 v;
                    v.x = acc[m][nb][0] + bb.x;
                    v.y = acc[m][nb][1] + bb.y;
                    __stcs(reinterpret_cast<float2*>(out + (size_t)r0 * 64 + col), v);
                }
                if (r0 + 8 < N_ROWS) {
                    float2 v;
                    v.x = acc[m][nb][2] + bb.x;
                    v.y = acc[m][nb][3] + bb.y;
                    __stcs(reinterpret_cast<float2*>(out + (size_t)(r0 + 8) * 64 + col), v);
                }
                acc[m][nb][0] = acc[m][nb][1] = acc[m][nb][2] = acc[m][nb][3] = 0.0f;
            }
        }
        __syncwarp();

        if (!nv) break;
        tile = ntile;
        base2 = nbase2;
        ilc = iln;
        irc = irn;
        cur ^= 1;
    }
}

extern "C" void kernel_launch(void* const* d_in, const int* in_sizes, int n_in,
                              void* d_out, int out_size) {
    const float* x  = (const float*)d_in[0];
    const int*   li = (const int*)d_in[1];
    const int*   ri = (const int*)d_in[2];
    const float* W  = (const float*)d_in[3];
    const float* b  = (const float*)d_in[4];
    float* out = (float*)d_out;

    cudaFuncSetAttribute(polyconv_kernel,
                         cudaFuncAttributeMaxDynamicSharedMemorySize, SMEM_TOTAL);
    polyconv_kernel<<<GRID, NTHREADS, SMEM_TOTAL>>>(x, li, ri, W, b, out);
}

// round 11
// speedup vs baseline: 1.2854x; 1.2854x over previous
#include <cuda_runtime.h>
#include <cstdint>

#define N_ROWS 1000000
#define NTHREADS 256
#define WARPS 8
#define ROWS_PER_WARP 32
#define TILE_ROWS 256
#define NTILES ((N_ROWS + TILE_ROWS - 1) / TILE_ROWS)   // 3907
#define GRID 152

// smem: W repacked [3][8ks][4q][32j] uint4 = 49152 B
//       A: per warp 2 buffers x (32 rows x 64 fp32) = 2 x 8192 B
//       bias 256 B
#define SMEM_W_BYTES  49152
#define SMEM_A_OFF    SMEM_W_BYTES
#define SMEM_A_BYTES  (WARPS * 2 * 8192)
#define SMEM_BIAS_OFF (SMEM_A_OFF + SMEM_A_BYTES)
#define SMEM_TOTAL    (SMEM_BIAS_OFF + 256)             // 180480 -> 1 CTA/SM

__device__ __forceinline__ uint32_t tf32r(float f) {
    uint32_t u;
    asm("cvt.rna.tf32.f32 %0, %1;" : "=r"(u) : "f"(f));
    return u;
}

__device__ __forceinline__ uint32_t smem_u32(const void* p) {
    uint32_t a;
    asm("{ .reg .u64 t; cvta.to.shared.u64 t, %1; cvt.u32.u64 %0, t; }"
        : "=r"(a) : "l"(p));
    return a;
}

__device__ __forceinline__ void mma1688(float* d, const uint32_t* a, uint32_t b0, uint32_t b1) {
    asm volatile(
        "mma.sync.aligned.m16n8k8.row.col.f32.tf32.tf32.f32 "
        "{%0,%1,%2,%3}, {%4,%5,%6,%7}, {%8,%9}, {%0,%1,%2,%3};"
        : "+f"(d[0]), "+f"(d[1]), "+f"(d[2]), "+f"(d[3])
        : "r"(a[0]), "r"(a[1]), "r"(a[2]), "r"(a[3]), "r"(b0), "r"(b1));
}

__device__ __forceinline__ void cpasync16(uint32_t dst, const void* src) {
    asm volatile("cp.async.cg.shared.global [%0], [%1], 16;" :: "r"(dst), "l"(src));
}
__device__ __forceinline__ void cp_commit() {
    asm volatile("cp.async.commit_group;" ::: "memory");
}
__device__ __forceinline__ void cp_wait1() {
    asm volatile("cp.async.wait_group 1;" ::: "memory");
}

// Gather 32 rows; 16 lanes cover one row's 16 chunks -> 2 contiguous-dst rows per
// cp.async step (4 cache lines each). Row indices broadcast via shfl.
// dst chunk swizzle: c -> c ^ (row & 15).
__device__ __forceinline__ void issue_stage_idx(uint32_t bufb, const float* __restrict__ x,
                                                int idxreg, int l) {
    const int sub = l >> 4;
    const int c = l & 15;
#pragma unroll
    for (int i = 0; i < 16; i++) {
        const int rl = 2 * i + sub;  // row within 32-row tile
        const int src = __shfl_sync(0xffffffffu, idxreg, rl);
        const uint32_t dst = bufb + (uint32_t)rl * 256u + ((uint32_t)(c ^ (rl & 15)) << 4);
        cpasync16(dst, reinterpret_cast<const char*>(x + (size_t)src * 64) + c * 16);
    }
}

// Identity gather: rows base2 + rl (clamped).
__device__ __forceinline__ void issue_stage_id(uint32_t bufb, const float* __restrict__ x,
                                               int base2, int l) {
    const int sub = l >> 4;
    const int c = l & 15;
#pragma unroll
    for (int i = 0; i < 16; i++) {
        const int rl = 2 * i + sub;
        int src = base2 + rl;
        if (src >= N_ROWS) src = N_ROWS - 1;
        const uint32_t dst = bufb + (uint32_t)rl * 256u + ((uint32_t)(c ^ (rl & 15)) << 4);
        cpasync16(dst, reinterpret_cast<const char*>(x + (size_t)src * 64) + c * 16);
    }
}

// one t-stage: 32 rows x 64 cols x 64 k. A fp32 in smem (swizzled), cvt.rna here.
// B LDS swizzle ^(q<<1): conflict-free phases.
__device__ __forceinline__ void mma_stage(const float* __restrict__ sA,
                                          const uint4* __restrict__ sWt,
                                          float acc[2][8][4], int g, int q) {
#pragma unroll
    for (int ks = 0; ks < 8; ks++) {
        uint32_t a[2][4];
#pragma unroll
        for (int m = 0; m < 2; m++) {
            const int r0 = m * 16 + g;       // r0 & 15 == g
            const int r1 = r0 + 8;           // r1 & 15 == g + 8
            a[m][0] = tf32r(sA[r0 * 64 + (((2 * ks) ^ g) << 2) + q]);
            a[m][1] = tf32r(sA[r1 * 64 + (((2 * ks) ^ (g + 8)) << 2) + q]);
            a[m][2] = tf32r(sA[r0 * 64 + (((2 * ks + 1) ^ g) << 2) + q]);
            a[m][3] = tf32r(sA[r1 * 64 + (((2 * ks + 1) ^ (g + 8)) << 2) + q]);
        }
        const uint4* bp = sWt + (ks * 4 + q) * 32;
#pragma unroll
        for (int nbl = 0; nbl < 4; nbl++) {
            const uint4 bv = bp[(nbl * 8 + g) ^ (q << 1)];
            mma1688(acc[0][nbl], a[0], bv.x, bv.y);
            mma1688(acc[0][nbl + 4], a[0], bv.z, bv.w);
            mma1688(acc[1][nbl], a[1], bv.x, bv.y);
            mma1688(acc[1][nbl + 4], a[1], bv.z, bv.w);
        }
    }
}

__global__ void __launch_bounds__(NTHREADS, 1)
polyconv_kernel(const float* __restrict__ x,
                const int* __restrict__ li,
                const int* __restrict__ ri,
                const float* __restrict__ W,
                const float* __restrict__ bias,
                float* __restrict__ out) {
    extern __shared__ char smem[];
    uint4* sW4 = reinterpret_cast<uint4*>(smem);   // [3][8][4][32] uint4
    const int tid = threadIdx.x;
    const int w = tid >> 5;
    const int l = tid & 31;
    float* sA = reinterpret_cast<float*>(smem + SMEM_A_OFF + w * 16384);  // 2 bufs x 2048 fp32
    float* sbias = reinterpret_cast<float*>(smem + SMEM_BIAS_OFF);
    const uint32_t sAu = smem_u32(sA);

    // ---- stage W: sW4[t][ks][q][j] = (W[k][n], W[k+4][n], W[k][n+32], W[k+4][n+32]),
    //      n = j ^ (q<<1), k = ks*8+q ; W gmem: W[n][t*64 + k]
    for (int i = tid; i < 3 * 8 * 4 * 32; i += NTHREADS) {
        const int j = i & 31;
        const int q = (i >> 5) & 3;
        const int ks = (i >> 7) & 7;
        const int t = i >> 10;
        const int n = j ^ (q << 1);
        const int k = ks * 8 + q;
        const float* wp = W + t * 64 + k;
        uint4 v;
        v.x = tf32r(wp[n * 192]);
        v.y = tf32r(wp[n * 192 + 4]);
        v.z = tf32r(wp[(n + 32) * 192]);
        v.w = tf32r(wp[(n + 32) * 192 + 4]);
        sW4[i] = v;
    }
    if (tid < 64) sbias[tid] = bias[tid];
    __syncthreads();

    const int q = l & 3;
    const int g = l >> 2;

    float acc[2][8][4];
#pragma unroll
    for (int m = 0; m < 2; m++)
#pragma unroll
        for (int nb = 0; nb < 8; nb++)
#pragma unroll
            for (int jj = 0; jj < 4; jj++) acc[m][nb][jj] = 0.0f;

    // ---- prologue ----
    int tile = blockIdx.x;
    int base2 = tile * TILE_ROWS + w * ROWS_PER_WARP;
    int idxrow = base2 + l;
    if (idxrow >= N_ROWS) idxrow = N_ROWS - 1;
    int ilc = __ldg(li + idxrow);   // per-lane: index for row l of this warp tile
    int irc = __ldg(ri + idxrow);
    issue_stage_id(sAu, x, base2, l);
    cp_commit();
    uint32_t cur = 0;

    while (true) {
        const int ntile = tile + GRID;
        const bool nv = (ntile < NTILES);
        const int nbase2 = (nv ? ntile : tile) * TILE_ROWS + w * ROWS_PER_WARP;
        int nidxrow = nbase2 + l;
        if (nidxrow >= N_ROWS) nidxrow = N_ROWS - 1;
        const int iln = __ldg(li + nidxrow);
        const int irn = __ldg(ri + nidxrow);

        const float* bufc = sA + (cur ? 2048 : 0);
        const float* bufo = sA + (cur ? 0 : 2048);
        const uint32_t bufcu = sAu + (cur ? 8192u : 0u);
        const uint32_t bufou = sAu + (cur ? 0u : 8192u);

        // ---- t0 (x) ----
        issue_stage_idx(bufou, x, ilc, l);   // t1 -> other buf
        cp_commit();
        cp_wait1();
        __syncwarp();
        mma_stage(bufc, sW4, acc, g, q);
        __syncwarp();
        // ---- t1 (x[L]) ----
        issue_stage_idx(bufcu, x, irc, l);   // t2 -> cur buf
        cp_commit();
        cp_wait1();
        __syncwarp();
        mma_stage(bufo, sW4 + 1024, acc, g, q);
        __syncwarp();
        // ---- t2 (x[R]) ----
        issue_stage_id(bufou, x, nbase2, l); // next t0 -> other buf
        cp_commit();
        cp_wait1();
        __syncwarp();
        mma_stage(bufc, sW4 + 2048, acc, g, q);

        // ---- epilogue: bias + evict-first stores (keep L2 for x gathers) ----
        const int rowb = base2 + g;
#pragma unroll
        for (int nb = 0; nb < 8; nb++) {
            const int col = nb * 8 + q * 2;
            const float2 bb = *reinterpret_cast<const float2*>(sbias + col);
#pragma unroll
            for (int m = 0; m < 2; m++) {
                const int r0 = rowb + m * 16;
                if (r0 < N_ROWS) {
                    float2 v;
                    v.x = acc[m][nb][0] + bb.x;
                    v.y = acc[m][nb][1] + bb.y;
                    __stcs(reinterpret_cast<float2*>(out + (size_t)r0 * 64 + col), v);
                }
                if (r0 + 8 < N_ROWS) {
                    float2 v;
                    v.x = acc[m][nb][2] + bb.x;
                    v.y = acc[m][nb][3] + bb.y;
                    __stcs(reinterpret_cast<float2*>(out + (size_t)(r0 + 8) * 64 + col), v);
                }
                acc[m][nb][0] = acc[m][nb][1] = acc[m][nb][2] = acc[m][nb][3] = 0.0f;
            }
        }
        __syncwarp();

        if (!nv) break;
        tile = ntile;
        base2 = nbase2;
        ilc = iln;
        irc = irn;
        cur ^= 1;
    }
}

extern "C" void kernel_launch(void* const* d_in, const int* in_sizes, int n_in,
                              void* d_out, int out_size) {
    const float* x  = (const float*)d_in[0];
    const int*   li = (const int*)d_in[1];
    const int*   ri = (const int*)d_in[2];
    const float* W  = (const float*)d_in[3];
    const float* b  = (const float*)d_in[4];
    float* out = (float*)d_out;

    cudaFuncSetAttribute(polyconv_kernel,
                         cudaFuncAttributeMaxDynamicSharedMemorySize, SMEM_TOTAL);
    polyconv_kernel<<<GRID, NTHREADS, SMEM_TOTAL>>>(x, li, ri, W, b, out);
}